// round 6
// baseline (speedup 1.0000x reference)
#include <cuda_runtime.h>
#include <math.h>
#include <stdint.h>

#define S_LEN 2048
#define T_LEN 2048
#define BATCH 2
#define EDIM  1024
#define HEADS 16
#define HDIM  64
#define HD    (HEADS*HDIM)   /* 1024 */

// ---------------- scratch (static device globals; no allocation) ----------
__device__ float g_Q [BATCH*HEADS*S_LEN*HDIM];   // (B,H,S,D)
__device__ float g_K [BATCH*HEADS*T_LEN*HDIM];   // (B,H,T,D)
__device__ float g_V [BATCH*HEADS*T_LEN*HDIM];   // (B,H,T,D)
__device__ float g_AV[S_LEN*BATCH*HD];           // (S,B,HD)

// ---------------- tf32 split helpers --------------------------------------
__device__ __forceinline__ void split_tf32(float x, uint32_t& hi, uint32_t& lo) {
    asm("cvt.rna.tf32.f32 %0, %1;" : "=r"(hi) : "f"(x));
    float l = x - __uint_as_float(hi);
    asm("cvt.rna.tf32.f32 %0, %1;" : "=r"(lo) : "f"(l));
}
__device__ __forceinline__ void mma_tf32(float* c, uint32_t a0, uint32_t a1,
                                         uint32_t a2, uint32_t a3,
                                         uint32_t b0, uint32_t b1) {
    asm volatile(
        "mma.sync.aligned.m16n8k8.row.col.f32.tf32.tf32.f32 "
        "{%0,%1,%2,%3}, {%4,%5,%6,%7}, {%8,%9}, {%0,%1,%2,%3};"
        : "+f"(c[0]), "+f"(c[1]), "+f"(c[2]), "+f"(c[3])
        : "r"(a0), "r"(a1), "r"(a2), "r"(a3), "r"(b0), "r"(b1));
}

// ===========================================================================
// 3xTF32 GEMM body with PRE-SPLIT smem tiles (split once at store time).
// D(128x128) = A(Mx1024) @ B(1024xN) + bias. 8 warps (2m x 4n), m16n8k8.
// smem layout per buffer: Ah | Al | Bh | Bl, each 16x132 uint32.
// ===========================================================================
#define ARR 2112            /* 16*132 */
#define BUFSZ (4*ARR)       /* 8448 uint32 per buffer */

template<int MODE>
__device__ __forceinline__ void gemm_body(
    const float* __restrict__ A, const float* __restrict__ B,
    const float* __restrict__ bias, const float* __restrict__ u,
    float* __restrict__ out, int N, int m0, int n0, uint32_t* sm)
{
    const float* Ap = (MODE == 2) ? g_AV : A;

    const int tid  = threadIdx.x;
    const int wid  = tid >> 5, lane = tid & 31;
    const int g    = lane >> 2, tg = lane & 3;
    const int wm   = wid >> 2,  wn = wid & 3;

    const int aRow = tid >> 2;          // 0..63
    const int aCol = (tid & 3) * 4;     // 0,4,8,12
    const int bRow = tid >> 5;          // 0..7
    const int bCol = (tid & 31) * 4;    // 0..124

    float acc[4][4][4] = {};

    float4 pa0, pa1, pb0, pb1;
    #define GLOAD(k0) do { \
        pa0 = *(const float4*)(Ap + (size_t)(m0 + aRow)      * 1024 + (k0) + aCol); \
        pa1 = *(const float4*)(Ap + (size_t)(m0 + aRow + 64) * 1024 + (k0) + aCol); \
        pb0 = *(const float4*)(B  + (size_t)((k0) + bRow)     * N + n0 + bCol);      \
        pb1 = *(const float4*)(B  + (size_t)((k0) + bRow + 8) * N + n0 + bCol);      \
    } while (0)

    #define SSTORE(buf) do { \
        uint32_t* Ah = sm + (buf) * BUFSZ; \
        uint32_t* Al = Ah + ARR; \
        uint32_t* Bh = Ah + 2 * ARR; \
        uint32_t* Bl = Ah + 3 * ARR; \
        uint32_t h, l; \
        split_tf32(pa0.x, h, l); Ah[(aCol+0)*132 + aRow] = h; Al[(aCol+0)*132 + aRow] = l; \
        split_tf32(pa0.y, h, l); Ah[(aCol+1)*132 + aRow] = h; Al[(aCol+1)*132 + aRow] = l; \
        split_tf32(pa0.z, h, l); Ah[(aCol+2)*132 + aRow] = h; Al[(aCol+2)*132 + aRow] = l; \
        split_tf32(pa0.w, h, l); Ah[(aCol+3)*132 + aRow] = h; Al[(aCol+3)*132 + aRow] = l; \
        split_tf32(pa1.x, h, l); Ah[(aCol+0)*132 + aRow+64] = h; Al[(aCol+0)*132 + aRow+64] = l; \
        split_tf32(pa1.y, h, l); Ah[(aCol+1)*132 + aRow+64] = h; Al[(aCol+1)*132 + aRow+64] = l; \
        split_tf32(pa1.z, h, l); Ah[(aCol+2)*132 + aRow+64] = h; Al[(aCol+2)*132 + aRow+64] = l; \
        split_tf32(pa1.w, h, l); Ah[(aCol+3)*132 + aRow+64] = h; Al[(aCol+3)*132 + aRow+64] = l; \
        uint4 bh4, bl4; \
        split_tf32(pb0.x, bh4.x, bl4.x); split_tf32(pb0.y, bh4.y, bl4.y); \
        split_tf32(pb0.z, bh4.z, bl4.z); split_tf32(pb0.w, bh4.w, bl4.w); \
        *(uint4*)&Bh[bRow*132 + bCol] = bh4; \
        *(uint4*)&Bl[bRow*132 + bCol] = bl4; \
        split_tf32(pb1.x, bh4.x, bl4.x); split_tf32(pb1.y, bh4.y, bl4.y); \
        split_tf32(pb1.z, bh4.z, bl4.z); split_tf32(pb1.w, bh4.w, bl4.w); \
        *(uint4*)&Bh[(bRow+8)*132 + bCol] = bh4; \
        *(uint4*)&Bl[(bRow+8)*132 + bCol] = bl4; \
    } while (0)

    GLOAD(0);
    SSTORE(0);
    __syncthreads();

    const int NKB = 1024 / 16;
    for (int kb = 0; kb < NKB; kb++) {
        int buf = kb & 1;
        if (kb + 1 < NKB) GLOAD((kb + 1) * 16);

        uint32_t* Ah = sm + buf * BUFSZ;
        uint32_t* Al = Ah + ARR;
        uint32_t* Bh = Ah + 2 * ARR;
        uint32_t* Bl = Ah + 3 * ARR;

        #pragma unroll
        for (int ks = 0; ks < 16; ks += 8) {
            uint32_t ah[4][4], al[4][4];
            #pragma unroll
            for (int mt = 0; mt < 4; mt++) {
                int r = wm * 64 + mt * 16 + g;
                ah[mt][0] = Ah[(ks + tg) * 132 + r];
                ah[mt][1] = Ah[(ks + tg) * 132 + r + 8];
                ah[mt][2] = Ah[(ks + tg + 4) * 132 + r];
                ah[mt][3] = Ah[(ks + tg + 4) * 132 + r + 8];
                al[mt][0] = Al[(ks + tg) * 132 + r];
                al[mt][1] = Al[(ks + tg) * 132 + r + 8];
                al[mt][2] = Al[(ks + tg + 4) * 132 + r];
                al[mt][3] = Al[(ks + tg + 4) * 132 + r + 8];
            }
            uint32_t bh[4][2], bl[4][2];
            #pragma unroll
            for (int nt = 0; nt < 4; nt++) {
                int c = wn * 32 + nt * 8 + g;
                bh[nt][0] = Bh[(ks + tg) * 132 + c];
                bh[nt][1] = Bh[(ks + tg + 4) * 132 + c];
                bl[nt][0] = Bl[(ks + tg) * 132 + c];
                bl[nt][1] = Bl[(ks + tg + 4) * 132 + c];
            }
            #pragma unroll
            for (int mt = 0; mt < 4; mt++)
                #pragma unroll
                for (int nt = 0; nt < 4; nt++) {
                    float* c = acc[mt][nt];
                    mma_tf32(c, ah[mt][0], ah[mt][1], ah[mt][2], ah[mt][3],
                                bh[nt][0], bh[nt][1]);
                    mma_tf32(c, ah[mt][0], ah[mt][1], ah[mt][2], ah[mt][3],
                                bl[nt][0], bl[nt][1]);
                    mma_tf32(c, al[mt][0], al[mt][1], al[mt][2], al[mt][3],
                                bh[nt][0], bh[nt][1]);
                }
        }

        if (kb + 1 < NKB) SSTORE(1 - buf);
        __syncthreads();
    }
    #undef GLOAD
    #undef SSTORE

    // ---------------- epilogue: scatter C fragments ------------------------
    #pragma unroll
    for (int mt = 0; mt < 4; mt++) {
        #pragma unroll
        for (int nt = 0; nt < 4; nt++) {
            #pragma unroll
            for (int e = 0; e < 4; e++) {
                int m = m0 + wm * 64 + mt * 16 + g + ((e >> 1) ? 8 : 0);
                int n = n0 + wn * 32 + nt * 8 + tg * 2 + (e & 1);
                float v = acc[mt][nt][e] + __ldg(bias + n);
                int t = m >> 1, bb = m & 1;
                if (MODE == 0) {
                    if (n < HD) {
                        int h = n >> 6, d = n & 63;
                        g_K[(((size_t)(bb * HEADS + h)) * T_LEN + t) * HDIM + d] = v;
                    } else {
                        int nn = n - HD;
                        int h = nn >> 6, d = nn & 63;
                        g_V[(((size_t)(bb * HEADS + h)) * T_LEN + t) * HDIM + d] = v;
                    }
                } else if (MODE == 1) {
                    int h = n >> 6, d = n & 63;
                    g_Q[(((size_t)(bb * HEADS + h)) * S_LEN + t) * HDIM + d] =
                        v + __ldg(u + n);
                } else {
                    out[(size_t)m * EDIM + n] = v;
                }
            }
        }
    }
}

// merged kv + q projection: 512 kv CTAs then 256 q CTAs
__global__ __launch_bounds__(256) void proj_gemm(
    const float* __restrict__ enc, const float* __restrict__ Wkv,
    const float* __restrict__ bkv,
    const float* __restrict__ inp, const float* __restrict__ Wq,
    const float* __restrict__ bq,  const float* __restrict__ u)
{
    extern __shared__ uint32_t sm_u[];
    int bx = blockIdx.x;
    if (bx < 512) {
        int n0 = (bx & 15) * 128, m0 = (bx >> 4) * 128;
        gemm_body<0>(enc, Wkv, bkv, nullptr, nullptr, 2 * HD, m0, n0, sm_u);
    } else {
        int i = bx - 512;
        int n0 = (i & 7) * 128, m0 = (i >> 3) * 128;
        gemm_body<1>(inp, Wq, bq, u, nullptr, HD, m0, n0, sm_u);
    }
}

__global__ __launch_bounds__(256) void out_gemm(
    const float* __restrict__ Wp, const float* __restrict__ bp,
    float* __restrict__ out)
{
    extern __shared__ uint32_t sm_u[];
    int n0 = (blockIdx.x & 7) * 128, m0 = (blockIdx.x >> 3) * 128;
    gemm_body<2>(nullptr, Wp, bp, nullptr, out, HD, m0, n0, sm_u);
}

// ===========================================================================
// Tensor-core flash attention, 3xTF32 (unchanged from R5 — known good).
// ===========================================================================
#define PADW 68

__global__ __launch_bounds__(256) void attn_mma(const unsigned char* __restrict__ mask)
{
    extern __shared__ float sm[];
    float* Qh = sm;                    // [128][68]
    float* Ql = Qh + 128 * PADW;
    float* Kh = Ql + 128 * PADW;       // [d=64][t=68]
    float* Kl = Kh + 64 * PADW;
    float* Vh = Kl + 64 * PADW;        // [t=64][d=68]
    float* Vl = Vh + 64 * PADW;
    float* Ps = Vl + 64 * PADW;        // [128][68]

    const int bh = blockIdx.y;
    const int b  = bh >> 4;
    const int h  = bh & 15;
    const int s0 = blockIdx.x * 128;
    const int tid = threadIdx.x;
    const int wid = tid >> 5, lane = tid & 31;
    const int g   = lane >> 2, tg = lane & 3;
    const int rowA = wid * 16 + g;

    const float* Qg = g_Q + (size_t)bh * S_LEN * HDIM;
    const float* Kg = g_K + (size_t)bh * T_LEN * HDIM;
    const float* Vg = g_V + (size_t)bh * T_LEN * HDIM;

    #pragma unroll
    for (int it = 0; it < 8; it++) {
        int idx = tid + it * 256;
        int r = idx >> 4, c = (idx & 15) * 4;
        float4 q = *(const float4*)(Qg + (size_t)(s0 + r) * HDIM + c);
        uint32_t hx, lx, hy, ly, hz, lz, hw, lw;
        split_tf32(q.x, hx, lx); split_tf32(q.y, hy, ly);
        split_tf32(q.z, hz, lz); split_tf32(q.w, hw, lw);
        *(float4*)&Qh[r * PADW + c] = make_float4(__uint_as_float(hx), __uint_as_float(hy),
                                                  __uint_as_float(hz), __uint_as_float(hw));
        *(float4*)&Ql[r * PADW + c] = make_float4(__uint_as_float(lx), __uint_as_float(ly),
                                                  __uint_as_float(lz), __uint_as_float(lw));
    }

    float o[8][4] = {};
    float m0 = -1e30f, m1 = -1e30f, l0 = 0.f, l1 = 0.f;

    for (int j0 = 0; j0 < T_LEN; j0 += 64) {
        __syncthreads();
        uint32_t mor = 0;
        #pragma unroll
        for (int it = 0; it < 4; it++) {
            int idx = tid + it * 256;
            int r = idx >> 4, c = (idx & 15) * 4;
            float4 k = *(const float4*)(Kg + (size_t)(j0 + r) * HDIM + c);
            uint32_t hi, lo;
            split_tf32(k.x, hi, lo); Kh[(c + 0) * PADW + r] = __uint_as_float(hi); Kl[(c + 0) * PADW + r] = __uint_as_float(lo);
            split_tf32(k.y, hi, lo); Kh[(c + 1) * PADW + r] = __uint_as_float(hi); Kl[(c + 1) * PADW + r] = __uint_as_float(lo);
            split_tf32(k.z, hi, lo); Kh[(c + 2) * PADW + r] = __uint_as_float(hi); Kl[(c + 2) * PADW + r] = __uint_as_float(lo);
            split_tf32(k.w, hi, lo); Kh[(c + 3) * PADW + r] = __uint_as_float(hi); Kl[(c + 3) * PADW + r] = __uint_as_float(lo);
            float4 v = *(const float4*)(Vg + (size_t)(j0 + r) * HDIM + c);
            uint32_t hx, lx, hy, ly, hz, lz, hw, lw;
            split_tf32(v.x, hx, lx); split_tf32(v.y, hy, ly);
            split_tf32(v.z, hz, lz); split_tf32(v.w, hw, lw);
            *(float4*)&Vh[r * PADW + c] = make_float4(__uint_as_float(hx), __uint_as_float(hy),
                                                      __uint_as_float(hz), __uint_as_float(hw));
            *(float4*)&Vl[r * PADW + c] = make_float4(__uint_as_float(lx), __uint_as_float(ly),
                                                      __uint_as_float(lz), __uint_as_float(lw));
        }
        #pragma unroll
        for (int it = 0; it < 2; it++) {
            int idx = tid + it * 256;
            int r = idx >> 2, c16 = (idx & 3) * 16;
            uint4 mv = *(const uint4*)(mask + (size_t)(s0 + r) * T_LEN + j0 + c16);
            mor |= mv.x | mv.y | mv.z | mv.w;
        }
        int any_mask = __syncthreads_or((int)mor);

        float sc[8][4] = {};
        #pragma unroll
        for (int ks = 0; ks < 8; ks++) {
            int k0 = ks * 8;
            uint32_t ah[4], al[4];
            ah[0] = __float_as_uint(Qh[ rowA      * PADW + k0 + tg]);
            ah[1] = __float_as_uint(Qh[(rowA + 8) * PADW + k0 + tg]);
            ah[2] = __float_as_uint(Qh[ rowA      * PADW + k0 + tg + 4]);
            ah[3] = __float_as_uint(Qh[(rowA + 8) * PADW + k0 + tg + 4]);
            al[0] = __float_as_uint(Ql[ rowA      * PADW + k0 + tg]);
            al[1] = __float_as_uint(Ql[(rowA + 8) * PADW + k0 + tg]);
            al[2] = __float_as_uint(Ql[ rowA      * PADW + k0 + tg + 4]);
            al[3] = __float_as_uint(Ql[(rowA + 8) * PADW + k0 + tg + 4]);
            #pragma unroll
            for (int nt = 0; nt < 8; nt++) {
                int n = nt * 8 + g;
                uint32_t b0h = __float_as_uint(Kh[(k0 + tg)     * PADW + n]);
                uint32_t b1h = __float_as_uint(Kh[(k0 + tg + 4) * PADW + n]);
                uint32_t b0l = __float_as_uint(Kl[(k0 + tg)     * PADW + n]);
                uint32_t b1l = __float_as_uint(Kl[(k0 + tg + 4) * PADW + n]);
                mma_tf32(sc[nt], ah[0], ah[1], ah[2], ah[3], b0h, b1h);
                mma_tf32(sc[nt], ah[0], ah[1], ah[2], ah[3], b0l, b1l);
                mma_tf32(sc[nt], al[0], al[1], al[2], al[3], b0h, b1h);
            }
        }

        #pragma unroll
        for (int nt = 0; nt < 8; nt++) {
            sc[nt][0] *= 0.125f; sc[nt][1] *= 0.125f;
            sc[nt][2] *= 0.125f; sc[nt][3] *= 0.125f;
        }
        if (any_mask) {
            int sg0 = s0 + rowA, sg1 = sg0 + 8;
            #pragma unroll
            for (int nt = 0; nt < 8; nt++) {
                int cg = j0 + nt * 8 + tg * 2;
                const unsigned char* m0p = mask + (size_t)sg0 * T_LEN + cg;
                const unsigned char* m1p = mask + (size_t)sg1 * T_LEN + cg;
                if (m0p[0]) sc[nt][0] = -INFINITY;
                if (m0p[1]) sc[nt][1] = -INFINITY;
                if (m1p[0]) sc[nt][2] = -INFINITY;
                if (m1p[1]) sc[nt][3] = -INFINITY;
            }
        }

        float mx0 = -1e30f, mx1 = -1e30f;
        #pragma unroll
        for (int nt = 0; nt < 8; nt++) {
            mx0 = fmaxf(mx0, fmaxf(sc[nt][0], sc[nt][1]));
            mx1 = fmaxf(mx1, fmaxf(sc[nt][2], sc[nt][3]));
        }
        mx0 = fmaxf(mx0, __shfl_xor_sync(0xffffffffu, mx0, 1));
        mx0 = fmaxf(mx0, __shfl_xor_sync(0xffffffffu, mx0, 2));
        mx1 = fmaxf(mx1, __shfl_xor_sync(0xffffffffu, mx1, 1));
        mx1 = fmaxf(mx1, __shfl_xor_sync(0xffffffffu, mx1, 2));

        float mn0 = fmaxf(m0, mx0), mn1 = fmaxf(m1, mx1);
        float cr0 = __expf(m0 - mn0), cr1 = __expf(m1 - mn1);
        float ps0 = 0.f, ps1 = 0.f;
        #pragma unroll
        for (int nt = 0; nt < 8; nt++) {
            sc[nt][0] = __expf(sc[nt][0] - mn0);
            sc[nt][1] = __expf(sc[nt][1] - mn0);
            sc[nt][2] = __expf(sc[nt][2] - mn1);
            sc[nt][3] = __expf(sc[nt][3] - mn1);
            ps0 += sc[nt][0] + sc[nt][1];
            ps1 += sc[nt][2] + sc[nt][3];
        }
        ps0 += __shfl_xor_sync(0xffffffffu, ps0, 1);
        ps0 += __shfl_xor_sync(0xffffffffu, ps0, 2);
        ps1 += __shfl_xor_sync(0xffffffffu, ps1, 1);
        ps1 += __shfl_xor_sync(0xffffffffu, ps1, 2);
        l0 = l0 * cr0 + ps0; m0 = mn0;
        l1 = l1 * cr1 + ps1; m1 = mn1;
        #pragma unroll
        for (int nt = 0; nt < 8; nt++) {
            o[nt][0] *= cr0; o[nt][1] *= cr0;
            o[nt][2] *= cr1; o[nt][3] *= cr1;
        }

        #pragma unroll
        for (int nt = 0; nt < 8; nt++) {
            int c = nt * 8 + tg * 2;
            *(float2*)&Ps[ rowA      * PADW + c] = make_float2(sc[nt][0], sc[nt][1]);
            *(float2*)&Ps[(rowA + 8) * PADW + c] = make_float2(sc[nt][2], sc[nt][3]);
        }
        __syncwarp();

        #pragma unroll
        for (int ks = 0; ks < 8; ks++) {
            int k0 = ks * 8;
            uint32_t ah[4], al[4];
            split_tf32(Ps[ rowA      * PADW + k0 + tg],     ah[0], al[0]);
            split_tf32(Ps[(rowA + 8) * PADW + k0 + tg],     ah[1], al[1]);
            split_tf32(Ps[ rowA      * PADW + k0 + tg + 4], ah[2], al[2]);
            split_tf32(Ps[(rowA + 8) * PADW + k0 + tg + 4], ah[3], al[3]);
            #pragma unroll
            for (int nt = 0; nt < 8; nt++) {
                int n = nt * 8 + g;
                uint32_t b0h = __float_as_uint(Vh[(k0 + tg)     * PADW + n]);
                uint32_t b1h = __float_as_uint(Vh[(k0 + tg + 4) * PADW + n]);
                uint32_t b0l = __float_as_uint(Vl[(k0 + tg)     * PADW + n]);
                uint32_t b1l = __float_as_uint(Vl[(k0 + tg + 4) * PADW + n]);
                mma_tf32(o[nt], ah[0], ah[1], ah[2], ah[3], b0h, b1h);
                mma_tf32(o[nt], ah[0], ah[1], ah[2], ah[3], b0l, b1l);
                mma_tf32(o[nt], al[0], al[1], al[2], al[3], b0h, b1h);
            }
        }
    }

    float i0 = 1.f / l0, i1 = 1.f / l1;
    int sg0 = s0 + rowA, sg1 = sg0 + 8;
    #pragma unroll
    for (int nt = 0; nt < 8; nt++) {
        int d = nt * 8 + tg * 2;
        *(float2*)(g_AV + ((size_t)sg0 * BATCH + b) * HD + h * HDIM + d) =
            make_float2(o[nt][0] * i0, o[nt][1] * i0);
        *(float2*)(g_AV + ((size_t)sg1 * BATCH + b) * HD + h * HDIM + d) =
            make_float2(o[nt][2] * i1, o[nt][3] * i1);
    }
}

// ---------------------------------------------------------------------------
extern "C" void kernel_launch(void* const* d_in, const int* in_sizes, int n_in,
                              void* d_out, int out_size)
{
    const float* inputs = (const float*)d_in[0];
    const float* enc    = (const float*)d_in[2];
    const float* u      = (const float*)d_in[3];
    const unsigned char* mask = (const unsigned char*)d_in[5];
    const float* Wkv = (const float*)d_in[6];
    const float* bkv = (const float*)d_in[7];
    const float* Wq  = (const float*)d_in[8];
    const float* bq  = (const float*)d_in[9];
    const float* Wp  = (const float*)d_in[10];
    const float* bp  = (const float*)d_in[11];
    float* out = (float*)d_out;

    const int GSMEM = 2 * BUFSZ * 4;   // 67584 B
    const int ASMEM = (2 * 128 + 2 * 64 + 2 * 64 + 128) * PADW * 4;  // 174080 B
    cudaFuncSetAttribute(proj_gemm, cudaFuncAttributeMaxDynamicSharedMemorySize, GSMEM);
    cudaFuncSetAttribute(out_gemm,  cudaFuncAttributeMaxDynamicSharedMemorySize, GSMEM);
    cudaFuncSetAttribute(attn_mma,  cudaFuncAttributeMaxDynamicSharedMemorySize, ASMEM);

    dim3 blk(256);
    proj_gemm<<<768, blk, GSMEM>>>(enc, Wkv, bkv, inputs, Wq, bq, u);
    attn_mma<<<dim3(S_LEN / 128, BATCH * HEADS), blk, ASMEM>>>(mask);
    out_gemm<<<256, blk, GSMEM>>>(Wp, bp, out);
}

// round 7
// speedup vs baseline: 1.4051x; 1.4051x over previous
#include <cuda_runtime.h>
#include <math.h>
#include <stdint.h>

#define S_LEN 2048
#define T_LEN 2048
#define BATCH 2
#define EDIM  1024
#define HEADS 16
#define HDIM  64
#define HD    (HEADS*HDIM)   /* 1024 */

// ---------------- scratch (static device globals; no allocation) ----------
__device__ float g_Q [BATCH*HEADS*S_LEN*HDIM];   // (B,H,S,D)
__device__ float g_K [BATCH*HEADS*T_LEN*HDIM];   // (B,H,T,D)
__device__ float g_V [BATCH*HEADS*T_LEN*HDIM];   // (B,H,T,D)
__device__ float g_AV[S_LEN*BATCH*HD];           // (S,B,HD)

// ---------------- tf32 split helpers (GEMMs, R5 known-good) ---------------
__device__ __forceinline__ void split_tf32(float x, uint32_t& hi, uint32_t& lo) {
    asm("cvt.rna.tf32.f32 %0, %1;" : "=r"(hi) : "f"(x));
    float l = x - __uint_as_float(hi);
    asm("cvt.rna.tf32.f32 %0, %1;" : "=r"(lo) : "f"(l));
}
__device__ __forceinline__ void mma_tf32(float* c, uint32_t a0, uint32_t a1,
                                         uint32_t a2, uint32_t a3,
                                         uint32_t b0, uint32_t b1) {
    asm volatile(
        "mma.sync.aligned.m16n8k8.row.col.f32.tf32.tf32.f32 "
        "{%0,%1,%2,%3}, {%4,%5,%6,%7}, {%8,%9}, {%0,%1,%2,%3};"
        : "+f"(c[0]), "+f"(c[1]), "+f"(c[2]), "+f"(c[3])
        : "r"(a0), "r"(a1), "r"(a2), "r"(a3), "r"(b0), "r"(b1));
}

// ---------------- bf16 split helpers (attention) ---------------------------
__device__ __forceinline__ uint32_t bfbits(float x) {   // rn-even bf16, as fp32 bits
    uint32_t u = __float_as_uint(x);
    return (u + 0x7FFFu + ((u >> 16) & 1u)) & 0xFFFF0000u;
}
// split-and-pack a (even, odd) pair into bf16x2 hi word + bf16x2 residual word
__device__ __forceinline__ void sp2(float e, float o, uint32_t& hw, uint32_t& lw) {
    uint32_t he = bfbits(e), ho = bfbits(o);
    float re = e - __uint_as_float(he);
    float ro = o - __uint_as_float(ho);
    hw = __byte_perm(he, ho, 0x7632);
    lw = __byte_perm(bfbits(re), bfbits(ro), 0x7632);
}
__device__ __forceinline__ void mma_bf16(float* c, uint32_t a0, uint32_t a1,
                                         uint32_t a2, uint32_t a3,
                                         uint32_t b0, uint32_t b1) {
    asm volatile(
        "mma.sync.aligned.m16n8k16.row.col.f32.bf16.bf16.f32 "
        "{%0,%1,%2,%3}, {%4,%5,%6,%7}, {%8,%9}, {%0,%1,%2,%3};"
        : "+f"(c[0]), "+f"(c[1]), "+f"(c[2]), "+f"(c[3])
        : "r"(a0), "r"(a1), "r"(a2), "r"(a3), "r"(b0), "r"(b1));
}

// ===========================================================================
// 3xTF32 tensor-core GEMM (R5 form — known good)
// ===========================================================================
template<int MODE>
__global__ __launch_bounds__(256) void mma_gemm(
    const float* __restrict__ A, const float* __restrict__ B,
    const float* __restrict__ bias, const float* __restrict__ u,
    float* __restrict__ out, int N)
{
    __shared__ float As[2][16][132];
    __shared__ float Bs[2][16][132];

    const float* Ap = (MODE == 2) ? g_AV : A;

    const int tid  = threadIdx.x;
    const int wid  = tid >> 5, lane = tid & 31;
    const int g    = lane >> 2, tg = lane & 3;
    const int wm   = wid >> 2,  wn = wid & 3;
    const int m0   = blockIdx.y * 128, n0 = blockIdx.x * 128;

    const int aRow = tid >> 2;
    const int aCol = (tid & 3) * 4;
    const int bRow = tid >> 5;
    const int bCol = (tid & 31) * 4;

    float acc[4][4][4] = {};

    float4 pa0, pa1, pb0, pb1;
    #define GLOAD(k0) do { \
        pa0 = *(const float4*)(Ap + (size_t)(m0 + aRow)      * 1024 + (k0) + aCol); \
        pa1 = *(const float4*)(Ap + (size_t)(m0 + aRow + 64) * 1024 + (k0) + aCol); \
        pb0 = *(const float4*)(B  + (size_t)((k0) + bRow)     * N + n0 + bCol);      \
        pb1 = *(const float4*)(B  + (size_t)((k0) + bRow + 8) * N + n0 + bCol);      \
    } while (0)
    #define SSTORE(buf) do { \
        As[buf][aCol + 0][aRow]      = pa0.x; \
        As[buf][aCol + 1][aRow]      = pa0.y; \
        As[buf][aCol + 2][aRow]      = pa0.z; \
        As[buf][aCol + 3][aRow]      = pa0.w; \
        As[buf][aCol + 0][aRow + 64] = pa1.x; \
        As[buf][aCol + 1][aRow + 64] = pa1.y; \
        As[buf][aCol + 2][aRow + 64] = pa1.z; \
        As[buf][aCol + 3][aRow + 64] = pa1.w; \
        *(float4*)&Bs[buf][bRow][bCol]     = pb0; \
        *(float4*)&Bs[buf][bRow + 8][bCol] = pb1; \
    } while (0)

    GLOAD(0);
    SSTORE(0);
    __syncthreads();

    const int NKB = 1024 / 16;
    for (int kb = 0; kb < NKB; kb++) {
        int buf = kb & 1;
        if (kb + 1 < NKB) GLOAD((kb + 1) * 16);

        #pragma unroll
        for (int ks = 0; ks < 16; ks += 8) {
            uint32_t ahi[4][4], alo[4][4];
            #pragma unroll
            for (int mt = 0; mt < 4; mt++) {
                int r = wm * 64 + mt * 16 + g;
                split_tf32(As[buf][ks + tg][r],         ahi[mt][0], alo[mt][0]);
                split_tf32(As[buf][ks + tg][r + 8],     ahi[mt][1], alo[mt][1]);
                split_tf32(As[buf][ks + tg + 4][r],     ahi[mt][2], alo[mt][2]);
                split_tf32(As[buf][ks + tg + 4][r + 8], ahi[mt][3], alo[mt][3]);
            }
            uint32_t bhi[4][2], blo[4][2];
            #pragma unroll
            for (int nt = 0; nt < 4; nt++) {
                int c = wn * 32 + nt * 8 + g;
                split_tf32(Bs[buf][ks + tg][c],     bhi[nt][0], blo[nt][0]);
                split_tf32(Bs[buf][ks + tg + 4][c], bhi[nt][1], blo[nt][1]);
            }
            #pragma unroll
            for (int mt = 0; mt < 4; mt++)
                #pragma unroll
                for (int nt = 0; nt < 4; nt++) {
                    float* c = acc[mt][nt];
                    mma_tf32(c, ahi[mt][0], ahi[mt][1], ahi[mt][2], ahi[mt][3],
                                bhi[nt][0], bhi[nt][1]);
                    mma_tf32(c, ahi[mt][0], ahi[mt][1], ahi[mt][2], ahi[mt][3],
                                blo[nt][0], blo[nt][1]);
                    mma_tf32(c, alo[mt][0], alo[mt][1], alo[mt][2], alo[mt][3],
                                bhi[nt][0], bhi[nt][1]);
                }
        }

        if (kb + 1 < NKB) SSTORE(1 - buf);
        __syncthreads();
    }
    #undef GLOAD
    #undef SSTORE

    #pragma unroll
    for (int mt = 0; mt < 4; mt++) {
        #pragma unroll
        for (int nt = 0; nt < 4; nt++) {
            #pragma unroll
            for (int e = 0; e < 4; e++) {
                int m = m0 + wm * 64 + mt * 16 + g + ((e >> 1) ? 8 : 0);
                int n = n0 + wn * 32 + nt * 8 + tg * 2 + (e & 1);
                float v = acc[mt][nt][e] + __ldg(bias + n);
                int t = m >> 1, bb = m & 1;
                if (MODE == 0) {
                    if (n < HD) {
                        int h = n >> 6, d = n & 63;
                        g_K[(((size_t)(bb * HEADS + h)) * T_LEN + t) * HDIM + d] = v;
                    } else {
                        int nn = n - HD;
                        int h = nn >> 6, d = nn & 63;
                        g_V[(((size_t)(bb * HEADS + h)) * T_LEN + t) * HDIM + d] = v;
                    }
                } else if (MODE == 1) {
                    int h = n >> 6, d = n & 63;
                    g_Q[(((size_t)(bb * HEADS + h)) * S_LEN + t) * HDIM + d] =
                        v + __ldg(u + n);
                } else {
                    out[(size_t)m * EDIM + n] = v;
                }
            }
        }
    }
}

// ===========================================================================
// Flash attention, 3x-bf16 m16n8k16. CTA = 128 S-rows x one (b,h), 8 warps.
// T-tile = 64. Q fragments live in registers (split once).
// smem (uint32): Kh/Kl [32 dpair][68 t], Vh/Vl [32 tpair][68 d],
//                Ph/Pl [128 row][36 tpair]  -> 71680 B dynamic.
// ===========================================================================
#define PADT 68
#define PADP 36

__global__ __launch_bounds__(256) void attn_bf16(const unsigned char* __restrict__ mask)
{
    extern __shared__ uint32_t smu[];
    uint32_t* Kh = smu;
    uint32_t* Kl = Kh + 32 * PADT;
    uint32_t* Vh = Kl + 32 * PADT;
    uint32_t* Vl = Vh + 32 * PADT;
    uint32_t* Ph = Vl + 32 * PADT;
    uint32_t* Pl = Ph + 128 * PADP;

    const int bh = blockIdx.y;
    const int b  = bh >> 4;
    const int h  = bh & 15;
    const int s0 = blockIdx.x * 128;
    const int tid = threadIdx.x;
    const int wid = tid >> 5, lane = tid & 31;
    const int g   = lane >> 2, tg = lane & 3;
    const int rowA = wid * 16 + g;

    const float* Qg = g_Q + (size_t)bh * S_LEN * HDIM;
    const float* Kg = g_K + (size_t)bh * T_LEN * HDIM;
    const float* Vg = g_V + (size_t)bh * T_LEN * HDIM;

    // ---- Q fragments -> registers, split once ----
    uint32_t qh[4][4], ql[4][4];
    {
        const float* q0p = Qg + (size_t)(s0 + rowA) * HDIM;
        const float* q1p = Qg + (size_t)(s0 + rowA + 8) * HDIM;
        #pragma unroll
        for (int ks = 0; ks < 4; ks++) {
            int k0 = ks * 16 + 2 * tg;
            float2 q0 = *(const float2*)(q0p + k0);
            float2 q1 = *(const float2*)(q1p + k0);
            float2 q2 = *(const float2*)(q0p + k0 + 8);
            float2 q3 = *(const float2*)(q1p + k0 + 8);
            sp2(q0.x, q0.y, qh[ks][0], ql[ks][0]);
            sp2(q1.x, q1.y, qh[ks][1], ql[ks][1]);
            sp2(q2.x, q2.y, qh[ks][2], ql[ks][2]);
            sp2(q3.x, q3.y, qh[ks][3], ql[ks][3]);
        }
    }

    float o[8][4] = {};
    float m0 = -1e30f, m1 = -1e30f, l0 = 0.f, l1 = 0.f;

    for (int j0 = 0; j0 < T_LEN; j0 += 64) {
        __syncthreads();

        // ---- K loader: [t=64][d=64] -> Kh/Kl [dpair][t], split+pack once ----
        #pragma unroll
        for (int it = 0; it < 4; it++) {
            int idx = tid + it * 256;
            int r = idx >> 4, c = (idx & 15) * 4;
            float4 k = *(const float4*)(Kg + (size_t)(j0 + r) * HDIM + c);
            uint32_t h0, l0w, h1, l1w;
            sp2(k.x, k.y, h0, l0w);
            sp2(k.z, k.w, h1, l1w);
            int c2 = c >> 1;
            Kh[c2 * PADT + r] = h0; Kh[(c2 + 1) * PADT + r] = h1;
            Kl[c2 * PADT + r] = l0w; Kl[(c2 + 1) * PADT + r] = l1w;
        }
        // ---- V loader: pack pairs along t -> Vh/Vl [tpair][d] ----
        #pragma unroll
        for (int it = 0; it < 2; it++) {
            int idx = tid + it * 256;
            int r2 = idx >> 4, c = (idx & 15) * 4;
            float4 va = *(const float4*)(Vg + (size_t)(j0 + 2 * r2)     * HDIM + c);
            float4 vb = *(const float4*)(Vg + (size_t)(j0 + 2 * r2 + 1) * HDIM + c);
            uint4 wh, wl;
            sp2(va.x, vb.x, wh.x, wl.x);
            sp2(va.y, vb.y, wh.y, wl.y);
            sp2(va.z, vb.z, wh.z, wl.z);
            sp2(va.w, vb.w, wh.w, wl.w);
            *(uint4*)&Vh[r2 * PADT + c] = wh;
            *(uint4*)&Vl[r2 * PADT + c] = wl;
        }
        // ---- mask OR-scan ----
        uint32_t mor = 0;
        #pragma unroll
        for (int it = 0; it < 2; it++) {
            int idx = tid + it * 256;
            int r = idx >> 2, c16 = (idx & 3) * 16;
            uint4 mv = *(const uint4*)(mask + (size_t)(s0 + r) * T_LEN + j0 + c16);
            mor |= mv.x | mv.y | mv.z | mv.w;
        }
        int any_mask = __syncthreads_or((int)mor);

        // ---- S = Q K^T (3x bf16, k16) ----
        float sc[8][4] = {};
        #pragma unroll
        for (int ks = 0; ks < 4; ks++) {
            #pragma unroll
            for (int nt = 0; nt < 8; nt++) {
                int n = nt * 8 + g;
                uint32_t b0h = Kh[(ks * 8 + tg)     * PADT + n];
                uint32_t b1h = Kh[(ks * 8 + tg + 4) * PADT + n];
                uint32_t b0l = Kl[(ks * 8 + tg)     * PADT + n];
                uint32_t b1l = Kl[(ks * 8 + tg + 4) * PADT + n];
                mma_bf16(sc[nt], qh[ks][0], qh[ks][1], qh[ks][2], qh[ks][3], b0h, b1h);
                mma_bf16(sc[nt], qh[ks][0], qh[ks][1], qh[ks][2], qh[ks][3], b0l, b1l);
                mma_bf16(sc[nt], ql[ks][0], ql[ks][1], ql[ks][2], ql[ks][3], b0h, b1h);
            }
        }

        // ---- scale + (rare) mask ----
        #pragma unroll
        for (int nt = 0; nt < 8; nt++) {
            sc[nt][0] *= 0.125f; sc[nt][1] *= 0.125f;
            sc[nt][2] *= 0.125f; sc[nt][3] *= 0.125f;
        }
        if (any_mask) {
            int sg0 = s0 + rowA, sg1 = sg0 + 8;
            #pragma unroll
            for (int nt = 0; nt < 8; nt++) {
                int cg = j0 + nt * 8 + tg * 2;
                const unsigned char* m0p = mask + (size_t)sg0 * T_LEN + cg;
                const unsigned char* m1p = mask + (size_t)sg1 * T_LEN + cg;
                if (m0p[0]) sc[nt][0] = -INFINITY;
                if (m0p[1]) sc[nt][1] = -INFINITY;
                if (m1p[0]) sc[nt][2] = -INFINITY;
                if (m1p[1]) sc[nt][3] = -INFINITY;
            }
        }

        // ---- warp-local online softmax ----
        float mx0 = -1e30f, mx1 = -1e30f;
        #pragma unroll
        for (int nt = 0; nt < 8; nt++) {
            mx0 = fmaxf(mx0, fmaxf(sc[nt][0], sc[nt][1]));
            mx1 = fmaxf(mx1, fmaxf(sc[nt][2], sc[nt][3]));
        }
        mx0 = fmaxf(mx0, __shfl_xor_sync(0xffffffffu, mx0, 1));
        mx0 = fmaxf(mx0, __shfl_xor_sync(0xffffffffu, mx0, 2));
        mx1 = fmaxf(mx1, __shfl_xor_sync(0xffffffffu, mx1, 1));
        mx1 = fmaxf(mx1, __shfl_xor_sync(0xffffffffu, mx1, 2));

        float mn0 = fmaxf(m0, mx0), mn1 = fmaxf(m1, mx1);
        float cr0 = __expf(m0 - mn0), cr1 = __expf(m1 - mn1);
        float ps0 = 0.f, ps1 = 0.f;
        #pragma unroll
        for (int nt = 0; nt < 8; nt++) {
            sc[nt][0] = __expf(sc[nt][0] - mn0);
            sc[nt][1] = __expf(sc[nt][1] - mn0);
            sc[nt][2] = __expf(sc[nt][2] - mn1);
            sc[nt][3] = __expf(sc[nt][3] - mn1);
            ps0 += sc[nt][0] + sc[nt][1];
            ps1 += sc[nt][2] + sc[nt][3];
        }
        ps0 += __shfl_xor_sync(0xffffffffu, ps0, 1);
        ps0 += __shfl_xor_sync(0xffffffffu, ps0, 2);
        ps1 += __shfl_xor_sync(0xffffffffu, ps1, 1);
        ps1 += __shfl_xor_sync(0xffffffffu, ps1, 2);
        l0 = l0 * cr0 + ps0; m0 = mn0;
        l1 = l1 * cr1 + ps1; m1 = mn1;
        #pragma unroll
        for (int nt = 0; nt < 8; nt++) {
            o[nt][0] *= cr0; o[nt][1] *= cr0;
            o[nt][2] *= cr1; o[nt][3] *= cr1;
        }

        // ---- stage P split+packed (warp-private rows) ----
        #pragma unroll
        for (int nt = 0; nt < 8; nt++) {
            int c2 = nt * 4 + tg;
            uint32_t hw, lw;
            sp2(sc[nt][0], sc[nt][1], hw, lw);
            Ph[rowA * PADP + c2] = hw; Pl[rowA * PADP + c2] = lw;
            sp2(sc[nt][2], sc[nt][3], hw, lw);
            Ph[(rowA + 8) * PADP + c2] = hw; Pl[(rowA + 8) * PADP + c2] = lw;
        }
        __syncwarp();

        // ---- O += P V (3x bf16, k16) ----
        #pragma unroll
        for (int ks = 0; ks < 4; ks++) {
            uint32_t ah[4], al[4];
            ah[0] = Ph[ rowA      * PADP + ks * 8 + tg];
            ah[1] = Ph[(rowA + 8) * PADP + ks * 8 + tg];
            ah[2] = Ph[ rowA      * PADP + ks * 8 + tg + 4];
            ah[3] = Ph[(rowA + 8) * PADP + ks * 8 + tg + 4];
            al[0] = Pl[ rowA      * PADP + ks * 8 + tg];
            al[1] = Pl[(rowA + 8) * PADP + ks * 8 + tg];
            al[2] = Pl[ rowA      * PADP + ks * 8 + tg + 4];
            al[3] = Pl[(rowA + 8) * PADP + ks * 8 + tg + 4];
            #pragma unroll
            for (int nt = 0; nt < 8; nt++) {
                int n = nt * 8 + g;
                uint32_t b0h = Vh[(ks * 8 + tg)     * PADT + n];
                uint32_t b1h = Vh[(ks * 8 + tg + 4) * PADT + n];
                uint32_t b0l = Vl[(ks * 8 + tg)     * PADT + n];
                uint32_t b1l = Vl[(ks * 8 + tg + 4) * PADT + n];
                mma_bf16(o[nt], ah[0], ah[1], ah[2], ah[3], b0h, b1h);
                mma_bf16(o[nt], ah[0], ah[1], ah[2], ah[3], b0l, b1l);
                mma_bf16(o[nt], al[0], al[1], al[2], al[3], b0h, b1h);
            }
        }
    }

    // ---- epilogue: normalize + store (S,B,HD) ----
    float i0 = 1.f / l0, i1 = 1.f / l1;
    int sg0 = s0 + rowA, sg1 = sg0 + 8;
    #pragma unroll
    for (int nt = 0; nt < 8; nt++) {
        int d = nt * 8 + tg * 2;
        *(float2*)(g_AV + ((size_t)sg0 * BATCH + b) * HD + h * HDIM + d) =
            make_float2(o[nt][0] * i0, o[nt][1] * i0);
        *(float2*)(g_AV + ((size_t)sg1 * BATCH + b) * HD + h * HDIM + d) =
            make_float2(o[nt][2] * i1, o[nt][3] * i1);
    }
}

// ---------------------------------------------------------------------------
extern "C" void kernel_launch(void* const* d_in, const int* in_sizes, int n_in,
                              void* d_out, int out_size)
{
    const float* inputs = (const float*)d_in[0];
    const float* enc    = (const float*)d_in[2];
    const float* u      = (const float*)d_in[3];
    const unsigned char* mask = (const unsigned char*)d_in[5];
    const float* Wkv = (const float*)d_in[6];
    const float* bkv = (const float*)d_in[7];
    const float* Wq  = (const float*)d_in[8];
    const float* bq  = (const float*)d_in[9];
    const float* Wp  = (const float*)d_in[10];
    const float* bp  = (const float*)d_in[11];
    float* out = (float*)d_out;

    const int ASMEM = (4 * 32 * PADT + 2 * 128 * PADP) * 4;   // 71680 B
    cudaFuncSetAttribute(attn_bf16, cudaFuncAttributeMaxDynamicSharedMemorySize, ASMEM);

    dim3 blk(256);
    mma_gemm<0><<<dim3(16, 32), blk>>>(enc,    Wkv, bkv, nullptr, nullptr, 2 * HD);
    mma_gemm<1><<<dim3(8, 32),  blk>>>(inputs, Wq,  bq,  u,       nullptr, HD);
    attn_bf16<<<dim3(S_LEN / 128, BATCH * HEADS), blk, ASMEM>>>(mask);
    mma_gemm<2><<<dim3(8, 32),  blk>>>(nullptr, Wp,  bp,  nullptr, out,    HD);
}

// round 8
// speedup vs baseline: 1.8105x; 1.2885x over previous
#include <cuda_runtime.h>
#include <math.h>
#include <stdint.h>

#define S_LEN 2048
#define T_LEN 2048
#define BATCH 2
#define EDIM  1024
#define HEADS 16
#define HDIM  64
#define HD    (HEADS*HDIM)   /* 1024 */

// ---------------- scratch (static device globals; no allocation) ----------
__device__ float g_Q [BATCH*HEADS*S_LEN*HDIM];   // (B,H,S,D)
__device__ float g_K [BATCH*HEADS*T_LEN*HDIM];   // (B,H,T,D)
__device__ float g_V [BATCH*HEADS*T_LEN*HDIM];   // (B,H,T,D)
__device__ float g_AV[S_LEN*BATCH*HD];           // (S,B,HD)

// ---------------- bf16 split helpers ---------------------------------------
__device__ __forceinline__ uint32_t bfbits(float x) {   // rn-even bf16, as fp32 bits
    uint32_t u = __float_as_uint(x);
    return (u + 0x7FFFu + ((u >> 16) & 1u)) & 0xFFFF0000u;
}
// split-and-pack (even, odd) pair -> bf16x2 hi word + bf16x2 residual word
__device__ __forceinline__ void sp2(float e, float o, uint32_t& hw, uint32_t& lw) {
    uint32_t he = bfbits(e), ho = bfbits(o);
    float re = e - __uint_as_float(he);
    float ro = o - __uint_as_float(ho);
    hw = __byte_perm(he, ho, 0x7632);
    lw = __byte_perm(bfbits(re), bfbits(ro), 0x7632);
}
__device__ __forceinline__ void mma_bf16(float* c, uint32_t a0, uint32_t a1,
                                         uint32_t a2, uint32_t a3,
                                         uint32_t b0, uint32_t b1) {
    asm volatile(
        "mma.sync.aligned.m16n8k16.row.col.f32.bf16.bf16.f32 "
        "{%0,%1,%2,%3}, {%4,%5,%6,%7}, {%8,%9}, {%0,%1,%2,%3};"
        : "+f"(c[0]), "+f"(c[1]), "+f"(c[2]), "+f"(c[3])
        : "r"(a0), "r"(a1), "r"(a2), "r"(a3), "r"(b0), "r"(b1));
}

// ===========================================================================
// 3x-bf16 tensor-core GEMM: D(128x128) = A(Mx1024) @ B(1024xN) + bias.
// 8 warps (2m x 4n), warp tile 64x32, mma m16n8k16, K-chunk 16 (8 kpairs).
// smem: Ah/Al/Bh/Bl [2 buf][8 kpair][136] uint32 (bf16x2, k-pairs packed).
// MODE 0: kv -> scatter g_K/g_V.  MODE 1: q (+u) -> g_Q.  MODE 2: -> out.
// ===========================================================================
#define PADM 136

template<int MODE>
__global__ __launch_bounds__(256) void mma_gemm(
    const float* __restrict__ A, const float* __restrict__ B,
    const float* __restrict__ bias, const float* __restrict__ u,
    float* __restrict__ out, int N)
{
    __shared__ uint32_t Ah[2][8][PADM], Al[2][8][PADM];
    __shared__ uint32_t Bh[2][8][PADM], Bl[2][8][PADM];

    const float* Ap = (MODE == 2) ? g_AV : A;

    const int tid  = threadIdx.x;
    const int wid  = tid >> 5, lane = tid & 31;
    const int g    = lane >> 2, tg = lane & 3;
    const int wm   = wid >> 2,  wn = wid & 3;
    const int m0   = blockIdx.y * 128, n0 = blockIdx.x * 128;

    const int aRow = tid >> 2;          // 0..63
    const int aCol = (tid & 3) * 4;     // 0,4,8,12 (k offset)
    const int aKp  = (tid & 3) * 2;     // kpair 0,2,4,6
    const int bKp  = tid >> 5;          // kpair 0..7
    const int bCol = (tid & 31) * 4;    // 0..124

    float acc[4][4][4] = {};

    float4 pa0, pa1, pb0, pb1;
    #define GLOAD(k0) do { \
        pa0 = *(const float4*)(Ap + (size_t)(m0 + aRow)      * 1024 + (k0) + aCol); \
        pa1 = *(const float4*)(Ap + (size_t)(m0 + aRow + 64) * 1024 + (k0) + aCol); \
        pb0 = *(const float4*)(B  + (size_t)((k0) + 2 * bKp)     * N + n0 + bCol);   \
        pb1 = *(const float4*)(B  + (size_t)((k0) + 2 * bKp + 1) * N + n0 + bCol);   \
    } while (0)
    #define SSTORE(buf) do { \
        uint32_t hw, lw; \
        sp2(pa0.x, pa0.y, hw, lw); Ah[buf][aKp][aRow]          = hw; Al[buf][aKp][aRow]          = lw; \
        sp2(pa0.z, pa0.w, hw, lw); Ah[buf][aKp + 1][aRow]      = hw; Al[buf][aKp + 1][aRow]      = lw; \
        sp2(pa1.x, pa1.y, hw, lw); Ah[buf][aKp][aRow + 64]     = hw; Al[buf][aKp][aRow + 64]     = lw; \
        sp2(pa1.z, pa1.w, hw, lw); Ah[buf][aKp + 1][aRow + 64] = hw; Al[buf][aKp + 1][aRow + 64] = lw; \
        uint4 wh, wl; \
        sp2(pb0.x, pb1.x, wh.x, wl.x); \
        sp2(pb0.y, pb1.y, wh.y, wl.y); \
        sp2(pb0.z, pb1.z, wh.z, wl.z); \
        sp2(pb0.w, pb1.w, wh.w, wl.w); \
        *(uint4*)&Bh[buf][bKp][bCol] = wh; \
        *(uint4*)&Bl[buf][bKp][bCol] = wl; \
    } while (0)

    GLOAD(0);
    SSTORE(0);
    __syncthreads();

    const int NKB = 1024 / 16;   // 64 chunks
    for (int kb = 0; kb < NKB; kb++) {
        int buf = kb & 1;
        if (kb + 1 < NKB) GLOAD((kb + 1) * 16);

        uint32_t ah[4][4], al4[4][4];
        #pragma unroll
        for (int mt = 0; mt < 4; mt++) {
            int r = wm * 64 + mt * 16 + g;
            ah[mt][0]  = Ah[buf][tg][r];
            ah[mt][1]  = Ah[buf][tg][r + 8];
            ah[mt][2]  = Ah[buf][tg + 4][r];
            ah[mt][3]  = Ah[buf][tg + 4][r + 8];
            al4[mt][0] = Al[buf][tg][r];
            al4[mt][1] = Al[buf][tg][r + 8];
            al4[mt][2] = Al[buf][tg + 4][r];
            al4[mt][3] = Al[buf][tg + 4][r + 8];
        }
        uint32_t bh[4][2], bl4[4][2];
        #pragma unroll
        for (int nt = 0; nt < 4; nt++) {
            int c = wn * 32 + nt * 8 + g;
            bh[nt][0]  = Bh[buf][tg][c];
            bh[nt][1]  = Bh[buf][tg + 4][c];
            bl4[nt][0] = Bl[buf][tg][c];
            bl4[nt][1] = Bl[buf][tg + 4][c];
        }
        #pragma unroll
        for (int mt = 0; mt < 4; mt++)
            #pragma unroll
            for (int nt = 0; nt < 4; nt++) {
                float* c = acc[mt][nt];
                mma_bf16(c, ah[mt][0], ah[mt][1], ah[mt][2], ah[mt][3],
                            bh[nt][0], bh[nt][1]);
                mma_bf16(c, ah[mt][0], ah[mt][1], ah[mt][2], ah[mt][3],
                            bl4[nt][0], bl4[nt][1]);
                mma_bf16(c, al4[mt][0], al4[mt][1], al4[mt][2], al4[mt][3],
                            bh[nt][0], bh[nt][1]);
            }

        if (kb + 1 < NKB) SSTORE(1 - buf);
        __syncthreads();
    }
    #undef GLOAD
    #undef SSTORE

    // ---------------- epilogue: scatter C fragments ------------------------
    #pragma unroll
    for (int mt = 0; mt < 4; mt++) {
        #pragma unroll
        for (int nt = 0; nt < 4; nt++) {
            #pragma unroll
            for (int e = 0; e < 4; e++) {
                int m = m0 + wm * 64 + mt * 16 + g + ((e >> 1) ? 8 : 0);
                int n = n0 + wn * 32 + nt * 8 + tg * 2 + (e & 1);
                float v = acc[mt][nt][e] + __ldg(bias + n);
                int t = m >> 1, bb = m & 1;
                if (MODE == 0) {
                    if (n < HD) {
                        int h = n >> 6, d = n & 63;
                        g_K[(((size_t)(bb * HEADS + h)) * T_LEN + t) * HDIM + d] = v;
                    } else {
                        int nn = n - HD;
                        int h = nn >> 6, d = nn & 63;
                        g_V[(((size_t)(bb * HEADS + h)) * T_LEN + t) * HDIM + d] = v;
                    }
                } else if (MODE == 1) {
                    int h = n >> 6, d = n & 63;
                    g_Q[(((size_t)(bb * HEADS + h)) * S_LEN + t) * HDIM + d] =
                        v + __ldg(u + n);
                } else {
                    out[(size_t)m * EDIM + n] = v;
                }
            }
        }
    }
}

// ===========================================================================
// Flash attention, 3x-bf16 m16n8k16 (unchanged from R7 — known good).
// ===========================================================================
#define PADT 68
#define PADP 36

__global__ __launch_bounds__(256) void attn_bf16(const unsigned char* __restrict__ mask)
{
    extern __shared__ uint32_t smu[];
    uint32_t* Kh = smu;
    uint32_t* Kl = Kh + 32 * PADT;
    uint32_t* Vh = Kl + 32 * PADT;
    uint32_t* Vl = Vh + 32 * PADT;
    uint32_t* Ph = Vl + 32 * PADT;
    uint32_t* Pl = Ph + 128 * PADP;

    const int bh = blockIdx.y;
    const int b  = bh >> 4;
    const int h  = bh & 15;
    const int s0 = blockIdx.x * 128;
    const int tid = threadIdx.x;
    const int wid = tid >> 5, lane = tid & 31;
    const int g   = lane >> 2, tg = lane & 3;
    const int rowA = wid * 16 + g;

    const float* Qg = g_Q + (size_t)bh * S_LEN * HDIM;
    const float* Kg = g_K + (size_t)bh * T_LEN * HDIM;
    const float* Vg = g_V + (size_t)bh * T_LEN * HDIM;

    uint32_t qh[4][4], ql[4][4];
    {
        const float* q0p = Qg + (size_t)(s0 + rowA) * HDIM;
        const float* q1p = Qg + (size_t)(s0 + rowA + 8) * HDIM;
        #pragma unroll
        for (int ks = 0; ks < 4; ks++) {
            int k0 = ks * 16 + 2 * tg;
            float2 q0 = *(const float2*)(q0p + k0);
            float2 q1 = *(const float2*)(q1p + k0);
            float2 q2 = *(const float2*)(q0p + k0 + 8);
            float2 q3 = *(const float2*)(q1p + k0 + 8);
            sp2(q0.x, q0.y, qh[ks][0], ql[ks][0]);
            sp2(q1.x, q1.y, qh[ks][1], ql[ks][1]);
            sp2(q2.x, q2.y, qh[ks][2], ql[ks][2]);
            sp2(q3.x, q3.y, qh[ks][3], ql[ks][3]);
        }
    }

    float o[8][4] = {};
    float m0 = -1e30f, m1 = -1e30f, l0 = 0.f, l1 = 0.f;

    for (int j0 = 0; j0 < T_LEN; j0 += 64) {
        __syncthreads();

        #pragma unroll
        for (int it = 0; it < 4; it++) {
            int idx = tid + it * 256;
            int r = idx >> 4, c = (idx & 15) * 4;
            float4 k = *(const float4*)(Kg + (size_t)(j0 + r) * HDIM + c);
            uint32_t h0, l0w, h1, l1w;
            sp2(k.x, k.y, h0, l0w);
            sp2(k.z, k.w, h1, l1w);
            int c2 = c >> 1;
            Kh[c2 * PADT + r] = h0; Kh[(c2 + 1) * PADT + r] = h1;
            Kl[c2 * PADT + r] = l0w; Kl[(c2 + 1) * PADT + r] = l1w;
        }
        #pragma unroll
        for (int it = 0; it < 2; it++) {
            int idx = tid + it * 256;
            int r2 = idx >> 4, c = (idx & 15) * 4;
            float4 va = *(const float4*)(Vg + (size_t)(j0 + 2 * r2)     * HDIM + c);
            float4 vb = *(const float4*)(Vg + (size_t)(j0 + 2 * r2 + 1) * HDIM + c);
            uint4 wh, wl;
            sp2(va.x, vb.x, wh.x, wl.x);
            sp2(va.y, vb.y, wh.y, wl.y);
            sp2(va.z, vb.z, wh.z, wl.z);
            sp2(va.w, vb.w, wh.w, wl.w);
            *(uint4*)&Vh[r2 * PADT + c] = wh;
            *(uint4*)&Vl[r2 * PADT + c] = wl;
        }
        uint32_t mor = 0;
        #pragma unroll
        for (int it = 0; it < 2; it++) {
            int idx = tid + it * 256;
            int r = idx >> 2, c16 = (idx & 3) * 16;
            uint4 mv = *(const uint4*)(mask + (size_t)(s0 + r) * T_LEN + j0 + c16);
            mor |= mv.x | mv.y | mv.z | mv.w;
        }
        int any_mask = __syncthreads_or((int)mor);

        float sc[8][4] = {};
        #pragma unroll
        for (int ks = 0; ks < 4; ks++) {
            #pragma unroll
            for (int nt = 0; nt < 8; nt++) {
                int n = nt * 8 + g;
                uint32_t b0h = Kh[(ks * 8 + tg)     * PADT + n];
                uint32_t b1h = Kh[(ks * 8 + tg + 4) * PADT + n];
                uint32_t b0l = Kl[(ks * 8 + tg)     * PADT + n];
                uint32_t b1l = Kl[(ks * 8 + tg + 4) * PADT + n];
                mma_bf16(sc[nt], qh[ks][0], qh[ks][1], qh[ks][2], qh[ks][3], b0h, b1h);
                mma_bf16(sc[nt], qh[ks][0], qh[ks][1], qh[ks][2], qh[ks][3], b0l, b1l);
                mma_bf16(sc[nt], ql[ks][0], ql[ks][1], ql[ks][2], ql[ks][3], b0h, b1h);
            }
        }

        #pragma unroll
        for (int nt = 0; nt < 8; nt++) {
            sc[nt][0] *= 0.125f; sc[nt][1] *= 0.125f;
            sc[nt][2] *= 0.125f; sc[nt][3] *= 0.125f;
        }
        if (any_mask) {
            int sg0 = s0 + rowA, sg1 = sg0 + 8;
            #pragma unroll
            for (int nt = 0; nt < 8; nt++) {
                int cg = j0 + nt * 8 + tg * 2;
                const unsigned char* m0p = mask + (size_t)sg0 * T_LEN + cg;
                const unsigned char* m1p = mask + (size_t)sg1 * T_LEN + cg;
                if (m0p[0]) sc[nt][0] = -INFINITY;
                if (m0p[1]) sc[nt][1] = -INFINITY;
                if (m1p[0]) sc[nt][2] = -INFINITY;
                if (m1p[1]) sc[nt][3] = -INFINITY;
            }
        }

        float mx0 = -1e30f, mx1 = -1e30f;
        #pragma unroll
        for (int nt = 0; nt < 8; nt++) {
            mx0 = fmaxf(mx0, fmaxf(sc[nt][0], sc[nt][1]));
            mx1 = fmaxf(mx1, fmaxf(sc[nt][2], sc[nt][3]));
        }
        mx0 = fmaxf(mx0, __shfl_xor_sync(0xffffffffu, mx0, 1));
        mx0 = fmaxf(mx0, __shfl_xor_sync(0xffffffffu, mx0, 2));
        mx1 = fmaxf(mx1, __shfl_xor_sync(0xffffffffu, mx1, 1));
        mx1 = fmaxf(mx1, __shfl_xor_sync(0xffffffffu, mx1, 2));

        float mn0 = fmaxf(m0, mx0), mn1 = fmaxf(m1, mx1);
        float cr0 = __expf(m0 - mn0), cr1 = __expf(m1 - mn1);
        float ps0 = 0.f, ps1 = 0.f;
        #pragma unroll
        for (int nt = 0; nt < 8; nt++) {
            sc[nt][0] = __expf(sc[nt][0] - mn0);
            sc[nt][1] = __expf(sc[nt][1] - mn0);
            sc[nt][2] = __expf(sc[nt][2] - mn1);
            sc[nt][3] = __expf(sc[nt][3] - mn1);
            ps0 += sc[nt][0] + sc[nt][1];
            ps1 += sc[nt][2] + sc[nt][3];
        }
        ps0 += __shfl_xor_sync(0xffffffffu, ps0, 1);
        ps0 += __shfl_xor_sync(0xffffffffu, ps0, 2);
        ps1 += __shfl_xor_sync(0xffffffffu, ps1, 1);
        ps1 += __shfl_xor_sync(0xffffffffu, ps1, 2);
        l0 = l0 * cr0 + ps0; m0 = mn0;
        l1 = l1 * cr1 + ps1; m1 = mn1;
        #pragma unroll
        for (int nt = 0; nt < 8; nt++) {
            o[nt][0] *= cr0; o[nt][1] *= cr0;
            o[nt][2] *= cr1; o[nt][3] *= cr1;
        }

        #pragma unroll
        for (int nt = 0; nt < 8; nt++) {
            int c2 = nt * 4 + tg;
            uint32_t hw, lw;
            sp2(sc[nt][0], sc[nt][1], hw, lw);
            Ph[rowA * PADP + c2] = hw; Pl[rowA * PADP + c2] = lw;
            sp2(sc[nt][2], sc[nt][3], hw, lw);
            Ph[(rowA + 8) * PADP + c2] = hw; Pl[(rowA + 8) * PADP + c2] = lw;
        }
        __syncwarp();

        #pragma unroll
        for (int ks = 0; ks < 4; ks++) {
            uint32_t ah[4], al[4];
            ah[0] = Ph[ rowA      * PADP + ks * 8 + tg];
            ah[1] = Ph[(rowA + 8) * PADP + ks * 8 + tg];
            ah[2] = Ph[ rowA      * PADP + ks * 8 + tg + 4];
            ah[3] = Ph[(rowA + 8) * PADP + ks * 8 + tg + 4];
            al[0] = Pl[ rowA      * PADP + ks * 8 + tg];
            al[1] = Pl[(rowA + 8) * PADP + ks * 8 + tg];
            al[2] = Pl[ rowA      * PADP + ks * 8 + tg + 4];
            al[3] = Pl[(rowA + 8) * PADP + ks * 8 + tg + 4];
            #pragma unroll
            for (int nt = 0; nt < 8; nt++) {
                int n = nt * 8 + g;
                uint32_t b0h = Vh[(ks * 8 + tg)     * PADT + n];
                uint32_t b1h = Vh[(ks * 8 + tg + 4) * PADT + n];
                uint32_t b0l = Vl[(ks * 8 + tg)     * PADT + n];
                uint32_t b1l = Vl[(ks * 8 + tg + 4) * PADT + n];
                mma_bf16(o[nt], ah[0], ah[1], ah[2], ah[3], b0h, b1h);
                mma_bf16(o[nt], ah[0], ah[1], ah[2], ah[3], b0l, b1l);
                mma_bf16(o[nt], al[0], al[1], al[2], al[3], b0h, b1h);
            }
        }
    }

    float i0 = 1.f / l0, i1 = 1.f / l1;
    int sg0 = s0 + rowA, sg1 = sg0 + 8;
    #pragma unroll
    for (int nt = 0; nt < 8; nt++) {
        int d = nt * 8 + tg * 2;
        *(float2*)(g_AV + ((size_t)sg0 * BATCH + b) * HD + h * HDIM + d) =
            make_float2(o[nt][0] * i0, o[nt][1] * i0);
        *(float2*)(g_AV + ((size_t)sg1 * BATCH + b) * HD + h * HDIM + d) =
            make_float2(o[nt][2] * i1, o[nt][3] * i1);
    }
}

// ---------------------------------------------------------------------------
extern "C" void kernel_launch(void* const* d_in, const int* in_sizes, int n_in,
                              void* d_out, int out_size)
{
    const float* inputs = (const float*)d_in[0];
    const float* enc    = (const float*)d_in[2];
    const float* u      = (const float*)d_in[3];
    const unsigned char* mask = (const unsigned char*)d_in[5];
    const float* Wkv = (const float*)d_in[6];
    const float* bkv = (const float*)d_in[7];
    const float* Wq  = (const float*)d_in[8];
    const float* bq  = (const float*)d_in[9];
    const float* Wp  = (const float*)d_in[10];
    const float* bp  = (const float*)d_in[11];
    float* out = (float*)d_out;

    const int ASMEM = (4 * 32 * PADT + 2 * 128 * PADP) * 4;   // 71680 B
    cudaFuncSetAttribute(attn_bf16, cudaFuncAttributeMaxDynamicSharedMemorySize, ASMEM);

    dim3 blk(256);
    mma_gemm<0><<<dim3(16, 32), blk>>>(enc,    Wkv, bkv, nullptr, nullptr, 2 * HD);
    mma_gemm<1><<<dim3(8, 32),  blk>>>(inputs, Wq,  bq,  u,       nullptr, HD);
    attn_bf16<<<dim3(S_LEN / 128, BATCH * HEADS), blk, ASMEM>>>(mask);
    mma_gemm<2><<<dim3(8, 32),  blk>>>(nullptr, Wp,  bp,  nullptr, out,    HD);
}